// round 1
// baseline (speedup 1.0000x reference)
#include <cuda_runtime.h>
#include <cstdint>

#define Bsz 8
#define Nseq 1024
#define Cdim 768
#define Hh 12
#define HD 64
#define RANK 8
#define SCALE 0.125f
#define Mrows (Bsz * Nseq)          // 8192

// Scratch: Q,K,V,O buffers (each B*H*N*HD = 6291456 floats) + lora-down outputs
#define QKV_ELEMS (Bsz * Hh * Nseq * HD)   // 6291456
#define XA_ELEMS  (Mrows * 24)
#define OA_ELEMS  (Mrows * 8)
__device__ float g_scratch[(size_t)QKV_ELEMS * 4 + XA_ELEMS + OA_ELEMS];

// ---------------------------------------------------------------------------
// LoRA down-projection: out[n, a*8+r] = dot(in[n,:], A_a[r,:])  (K = 768)
// One block per row, one warp per (adapter, r) dot product.
// ---------------------------------------------------------------------------
__global__ void __launch_bounds__(768) lora_down_kernel(
    const float* __restrict__ in, float* __restrict__ out,
    const float* __restrict__ a0, const float* __restrict__ a1,
    const float* __restrict__ a2, int nA)
{
    __shared__ float row[Cdim];
    int n = blockIdx.x;
    row[threadIdx.x] = in[(size_t)n * Cdim + threadIdx.x];
    __syncthreads();
    int w = threadIdx.x >> 5, lane = threadIdx.x & 31;
    int nDots = nA * 8;
    if (w < nDots) {
        const float* a = ((w < 8) ? a0 : (w < 16) ? a1 : a2) + (size_t)(w & 7) * Cdim;
        float s = 0.f;
        #pragma unroll
        for (int c = lane; c < Cdim; c += 32) s += row[c] * a[c];
        #pragma unroll
        for (int off = 16; off; off >>= 1) s += __shfl_xor_sync(0xffffffffu, s, off);
        if (lane == 0) out[(size_t)n * nDots + w] = s;
    }
}

// ---------------------------------------------------------------------------
// Tiled NT GEMM: C[m,d] = sum_k A[m,k] * Bw[d,k]   (K = 768)
// 64x64 tile, BK=16, 256 threads, 4x4 per thread.
// mode 0: qkv epilogue (bias + lora-up + scatter to [B,H,N,HD], q *= SCALE)
// mode 1: proj epilogue (bias + lora-up, write row-major [M, 768])
// ---------------------------------------------------------------------------
__global__ void __launch_bounds__(256) gemm_nt_kernel(
    const float* __restrict__ A, const float* __restrict__ Bw, int K, int mode,
    const float* __restrict__ bias,
    const float* __restrict__ xa, int xa_stride,
    const float* __restrict__ wb_q, const float* __restrict__ wb_k,
    const float* __restrict__ wb_v,
    float* __restrict__ oq, float* __restrict__ ok, float* __restrict__ ov)
{
    __shared__ float As[16][64];
    __shared__ float Bs[16][64];
    int m0 = blockIdx.y * 64, n0 = blockIdx.x * 64;
    int t = threadIdx.x;
    int lr = t >> 2, ls = t & 3;   // load row / k-segment
    int tx = t & 15, ty = t >> 4;

    float acc[4][4] = {};
    const float* Ap = A  + (size_t)(m0 + lr) * K + ls * 4;
    const float* Bp = Bw + (size_t)(n0 + lr) * K + ls * 4;

    for (int k0 = 0; k0 < K; k0 += 16) {
        float4 a4 = *(const float4*)(Ap + k0);
        float4 b4 = *(const float4*)(Bp + k0);
        __syncthreads();
        As[ls*4+0][lr] = a4.x; As[ls*4+1][lr] = a4.y;
        As[ls*4+2][lr] = a4.z; As[ls*4+3][lr] = a4.w;
        Bs[ls*4+0][lr] = b4.x; Bs[ls*4+1][lr] = b4.y;
        Bs[ls*4+2][lr] = b4.z; Bs[ls*4+3][lr] = b4.w;
        __syncthreads();
        #pragma unroll
        for (int kk = 0; kk < 16; kk++) {
            float ar[4], br[4];
            *(float4*)ar = *(const float4*)&As[kk][ty * 4];
            *(float4*)br = *(const float4*)&Bs[kk][tx * 4];
            #pragma unroll
            for (int i = 0; i < 4; i++)
                #pragma unroll
                for (int j = 0; j < 4; j++)
                    acc[i][j] += ar[i] * br[j];
        }
    }

    if (mode == 0) {
        int s = n0 / Cdim;                 // whole 64-col tile is in one sector
        const float* wb = (s == 0) ? wb_q : (s == 1) ? wb_k : wb_v;
        float* dst = (s == 0) ? oq : (s == 1) ? ok : ov;
        int dd0 = n0 - s * Cdim;
        #pragma unroll
        for (int i = 0; i < 4; i++) {
            int m = m0 + ty * 4 + i;
            const float* xr = xa + (size_t)m * xa_stride + s * 8;
            float xl[8];
            #pragma unroll
            for (int r = 0; r < 8; r++) xl[r] = xr[r];
            int b = m >> 10, nn = m & 1023;
            #pragma unroll
            for (int j = 0; j < 4; j++) {
                int d  = n0 + tx * 4 + j;
                int dd = dd0 + tx * 4 + j;
                float v = acc[i][j] + bias[d];
                #pragma unroll
                for (int r = 0; r < 8; r++) v += xl[r] * wb[dd * 8 + r];
                if (s == 0) v *= SCALE;
                int h = dd >> 6, hd = dd & 63;
                dst[(((size_t)(b * Hh + h) * Nseq) + nn) * HD + hd] = v;
            }
        }
    } else {
        #pragma unroll
        for (int i = 0; i < 4; i++) {
            int m = m0 + ty * 4 + i;
            const float* xr = xa + (size_t)m * 8;
            float xl[8];
            #pragma unroll
            for (int r = 0; r < 8; r++) xl[r] = xr[r];
            float* op = oq + (size_t)m * Cdim;
            #pragma unroll
            for (int j = 0; j < 4; j++) {
                int d = n0 + tx * 4 + j;
                float v = acc[i][j] + bias[d];
                #pragma unroll
                for (int r = 0; r < 8; r++) v += xl[r] * wb_q[d * 8 + r];
                op[d] = v;
            }
        }
    }
}

// ---------------------------------------------------------------------------
// Attention: one thread per query row (q already scaled by SCALE).
// Block = 128 q-rows of one (b,h). Loop over 16 K/V tiles of 64 keys.
// ---------------------------------------------------------------------------
__global__ void __launch_bounds__(128) attn_kernel(
    const float* __restrict__ Q, const float* __restrict__ Kf,
    const float* __restrict__ V, float* __restrict__ O)
{
    __shared__ float kb[64 * 64];
    __shared__ float vb[64 * 64];
    int bh = blockIdx.x >> 3;      // 0..95
    int qt = blockIdx.x & 7;
    int tid = threadIdx.x;

    const float* qp = Q + ((size_t)bh * Nseq + qt * 128 + tid) * HD;
    const float* kp = Kf + (size_t)bh * Nseq * HD;
    const float* vp = V  + (size_t)bh * Nseq * HD;

    float q[64], o[64];
    #pragma unroll
    for (int i = 0; i < 16; i++) {
        float4 t4 = ((const float4*)qp)[i];
        q[4*i] = t4.x; q[4*i+1] = t4.y; q[4*i+2] = t4.z; q[4*i+3] = t4.w;
    }
    #pragma unroll
    for (int d = 0; d < 64; d++) o[d] = 0.f;

    float mval = -1e30f, l = 0.f;

    for (int kt = 0; kt < 16; kt++) {
        __syncthreads();
        const float4* ksrc = (const float4*)(kp + (size_t)kt * 64 * 64);
        const float4* vsrc = (const float4*)(vp + (size_t)kt * 64 * 64);
        #pragma unroll
        for (int i = 0; i < 8; i++) {
            int idx = tid + i * 128;       // 1024 float4 = 4096 floats
            ((float4*)kb)[idx] = ksrc[idx];
            ((float4*)vb)[idx] = vsrc[idx];
        }
        __syncthreads();
        for (int j = 0; j < 64; j++) {
            const float* krow = kb + j * 64;
            float s0 = 0.f, s1 = 0.f, s2 = 0.f, s3 = 0.f;
            #pragma unroll
            for (int d = 0; d < 64; d += 4) {
                s0 += q[d]   * krow[d];
                s1 += q[d+1] * krow[d+1];
                s2 += q[d+2] * krow[d+2];
                s3 += q[d+3] * krow[d+3];
            }
            float s = (s0 + s1) + (s2 + s3);
            if (s > mval) {
                float c = __expf(mval - s);
                mval = s;
                l *= c;
                #pragma unroll
                for (int d = 0; d < 64; d++) o[d] *= c;
            }
            float p = __expf(s - mval);
            l += p;
            const float* vrow = vb + j * 64;
            #pragma unroll
            for (int d = 0; d < 64; d++) o[d] += p * vrow[d];
        }
    }

    float inv = 1.f / l;
    int b = bh / Hh, h = bh % Hh;
    int nn = qt * 128 + tid;
    float* op = O + ((size_t)b * Nseq + nn) * Cdim + h * HD;
    #pragma unroll
    for (int i = 0; i < 16; i++) {
        float4 t4;
        t4.x = o[4*i]   * inv; t4.y = o[4*i+1] * inv;
        t4.z = o[4*i+2] * inv; t4.w = o[4*i+3] * inv;
        ((float4*)op)[i] = t4;
    }
}

// ---------------------------------------------------------------------------
extern "C" void kernel_launch(void* const* d_in, const int* in_sizes, int n_in,
                              void* d_out, int out_size)
{
    const float* x      = (const float*)d_in[0];
    const float* w_qkv  = (const float*)d_in[1];
    const float* b_qkv  = (const float*)d_in[2];
    const float* w_proj = (const float*)d_in[3];
    const float* b_proj = (const float*)d_in[4];
    const float* q_a = (const float*)d_in[5];
    const float* q_b = (const float*)d_in[6];
    const float* k_a = (const float*)d_in[7];
    const float* k_b = (const float*)d_in[8];
    const float* v_a = (const float*)d_in[9];
    const float* v_b = (const float*)d_in[10];
    const float* o_a = (const float*)d_in[11];
    const float* o_b = (const float*)d_in[12];
    float* out = (float*)d_out;

    void* sym = nullptr;
    cudaGetSymbolAddress(&sym, g_scratch);
    float* base = (float*)sym;
    float* Qb = base;
    float* Kb = base + (size_t)QKV_ELEMS;
    float* Vb = base + (size_t)QKV_ELEMS * 2;
    float* Ob = base + (size_t)QKV_ELEMS * 3;
    float* XA = base + (size_t)QKV_ELEMS * 4;
    float* OA = XA + XA_ELEMS;

    // 1) LoRA down for q/k/v adapters: XA[m, 24]
    lora_down_kernel<<<Mrows, 768>>>(x, XA, q_a, k_a, v_a, 3);

    // 2) QKV GEMM + bias + LoRA-up + scatter (+ SCALE folded into q)
    gemm_nt_kernel<<<dim3(36, 128), 256>>>(x, w_qkv, Cdim, 0, b_qkv,
                                           XA, 24, q_b, k_b, v_b, Qb, Kb, Vb);

    // 3) Attention
    attn_kernel<<<Bsz * Hh * 8, 128>>>(Qb, Kb, Vb, Ob);

    // 4) LoRA down for o adapter: OA[m, 8]
    lora_down_kernel<<<Mrows, 768>>>(Ob, OA, o_a, o_a, o_a, 1);

    // 5) Output projection + bias + LoRA-up
    gemm_nt_kernel<<<dim3(12, 128), 256>>>(Ob, w_proj, Cdim, 1, b_proj,
                                           OA, 8, o_b, o_b, o_b, out, out, out);
}

// round 3
// speedup vs baseline: 1.5748x; 1.5748x over previous
#include <cuda_runtime.h>
#include <cuda_bf16.h>
#include <cstdint>

#define Bsz 8
#define Nseq 1024
#define Cdim 768
#define Hh 12
#define HD 64
#define RANK 8
#define SCALE 0.125f
#define Mrows (Bsz * Nseq)          // 8192

#define QKV_ELEMS (Bsz * Hh * Nseq * HD)   // 6291456
#define XA_ELEMS  (Mrows * 24)
#define OA_ELEMS  (Mrows * 8)

// float offsets into g_scratch
#define OFF_XA   ((size_t)QKV_ELEMS * 4)                 // 25165824
#define OFF_OA   (OFF_XA + XA_ELEMS)
#define OFF_XHI  (OFF_OA + OA_ELEMS)                     // bf16 regions (in float slots)
#define OFF_XLO  (OFF_XHI + QKV_ELEMS / 2)
#define OFF_WQH  (OFF_XLO + QKV_ELEMS / 2)
#define OFF_WQL  (OFF_WQH + (3 * Cdim * Cdim) / 2)
#define OFF_WPH  (OFF_WQL + (3 * Cdim * Cdim) / 2)
#define OFF_WPL  (OFF_WPH + (Cdim * Cdim) / 2)
#define OFF_OHI  (OFF_WPL + (Cdim * Cdim) / 2)
#define OFF_OLO  (OFF_OHI + QKV_ELEMS / 2)
#define SCRATCH_FLOATS (OFF_OLO + QKV_ELEMS / 2)

__device__ float g_scratch[SCRATCH_FLOATS];

// ===========================================================================
// bf16 split: hi = bf16(v), lo = bf16(v - hi)
// ===========================================================================
__global__ void __launch_bounds__(256) split_kernel(
    const float* __restrict__ in, __nv_bfloat16* __restrict__ hi,
    __nv_bfloat16* __restrict__ lo)
{
    int i = blockIdx.x * 256 + threadIdx.x;
    float4 v = ((const float4*)in)[i];
    __nv_bfloat16 h0 = __float2bfloat16(v.x);
    __nv_bfloat16 h1 = __float2bfloat16(v.y);
    __nv_bfloat16 h2 = __float2bfloat16(v.z);
    __nv_bfloat16 h3 = __float2bfloat16(v.w);
    __nv_bfloat162 hp0; hp0.x = h0; hp0.y = h1;
    __nv_bfloat162 hp1; hp1.x = h2; hp1.y = h3;
    __nv_bfloat162 lp0, lp1;
    lp0.x = __float2bfloat16(v.x - __bfloat162float(h0));
    lp0.y = __float2bfloat16(v.y - __bfloat162float(h1));
    lp1.x = __float2bfloat16(v.z - __bfloat162float(h2));
    lp1.y = __float2bfloat16(v.w - __bfloat162float(h3));
    ((__nv_bfloat162*)hi)[i * 2]     = hp0;
    ((__nv_bfloat162*)hi)[i * 2 + 1] = hp1;
    ((__nv_bfloat162*)lo)[i * 2]     = lp0;
    ((__nv_bfloat162*)lo)[i * 2 + 1] = lp1;
}

// ===========================================================================
// LoRA down-projection
// ===========================================================================
__global__ void __launch_bounds__(768) lora_down_kernel(
    const float* __restrict__ in, float* __restrict__ out,
    const float* __restrict__ a0, const float* __restrict__ a1,
    const float* __restrict__ a2, int nA)
{
    __shared__ float row[Cdim];
    int n = blockIdx.x;
    row[threadIdx.x] = in[(size_t)n * Cdim + threadIdx.x];
    __syncthreads();
    int w = threadIdx.x >> 5, lane = threadIdx.x & 31;
    int nDots = nA * 8;
    if (w < nDots) {
        const float* a = ((w < 8) ? a0 : (w < 16) ? a1 : a2) + (size_t)(w & 7) * Cdim;
        float s = 0.f;
        #pragma unroll
        for (int c = lane; c < Cdim; c += 32) s += row[c] * a[c];
        #pragma unroll
        for (int off = 16; off; off >>= 1) s += __shfl_xor_sync(0xffffffffu, s, off);
        if (lane == 0) out[(size_t)n * nDots + w] = s;
    }
}

// ===========================================================================
// bf16x3 split-precision NT GEMM via mma.sync m16n8k16.
// C[m,d] = sum_k A[m,k]*B[d,k], K=768, tiles 128x128, BK=32, 8 warps (64x32).
// MODE 0: qkv epilogue (bias + lora-up + scatter to [B,H,N,HD], q *= SCALE)
// MODE 1: proj epilogue (bias + lora-up, row-major out)
// ===========================================================================
#define GK768_U32 384          // row stride of split arrays in u32 (768 halves)
#define SROW 20                // smem row stride in u32 (32 halves + pad 8)
#define STAGE_U32 (4 * 128 * SROW)   // 10240
#define GEMM_SMEM (2 * STAGE_U32 * 4)  // 81920 bytes

__device__ __forceinline__ void mma_bf16(float* c, const uint32_t* a, const uint32_t* b) {
    asm volatile("mma.sync.aligned.m16n8k16.row.col.f32.bf16.bf16.f32 "
        "{%0,%1,%2,%3}, {%4,%5,%6,%7}, {%8,%9}, {%0,%1,%2,%3};"
        : "+f"(c[0]), "+f"(c[1]), "+f"(c[2]), "+f"(c[3])
        : "r"(a[0]), "r"(a[1]), "r"(a[2]), "r"(a[3]), "r"(b[0]), "r"(b[1]));
}

template <int MODE>
__global__ void __launch_bounds__(256) gemm_bf16x3_kernel(
    const uint32_t* __restrict__ Ahi, const uint32_t* __restrict__ Alo,
    const uint32_t* __restrict__ Bhi, const uint32_t* __restrict__ Blo,
    const float* __restrict__ bias,
    const float* __restrict__ xa, int xa_stride,
    const float* __restrict__ wb_q, const float* __restrict__ wb_k,
    const float* __restrict__ wb_v,
    float* __restrict__ oq, float* __restrict__ ok, float* __restrict__ ov)
{
    extern __shared__ uint32_t sm[];
    int tid = threadIdx.x;
    int wid = tid >> 5, lane = tid & 31;
    int wm = wid >> 2, wn = wid & 3;      // warp grid 2(m) x 4(n)
    int m0 = blockIdx.y * 128, n0 = blockIdx.x * 128;
    int g = lane >> 2, tg = lane & 3;

    float C[4][4][4];
    #pragma unroll
    for (int a = 0; a < 4; a++)
        #pragma unroll
        for (int b = 0; b < 4; b++)
            #pragma unroll
            for (int q = 0; q < 4; q++) C[a][b][q] = 0.f;

    int row_l = tid >> 2, kq_l = tid & 3;           // loader indices (i=0)
    int row_h = (tid + 256) >> 2, kq_h = tid & 3;   // i=1

    uint4 rg[8];
    // prologue: chunk 0
    {
        const uint32_t off = kq_l * 4;
        size_t ar0 = (size_t)(m0 + row_l) * GK768_U32 + off;
        size_t br0 = (size_t)(n0 + row_l) * GK768_U32 + off;
        size_t ar1 = (size_t)(m0 + row_h) * GK768_U32 + off;
        size_t br1 = (size_t)(n0 + row_h) * GK768_U32 + off;
        rg[0] = *(const uint4*)(Ahi + ar0); rg[1] = *(const uint4*)(Alo + ar0);
        rg[2] = *(const uint4*)(Bhi + br0); rg[3] = *(const uint4*)(Blo + br0);
        rg[4] = *(const uint4*)(Ahi + ar1); rg[5] = *(const uint4*)(Alo + ar1);
        rg[6] = *(const uint4*)(Bhi + br1); rg[7] = *(const uint4*)(Blo + br1);
    }
    {
        uint32_t* st = sm;
        uint32_t o0 = row_l * SROW + kq_l * 4;
        uint32_t o1 = row_h * SROW + kq_h * 4;
        *(uint4*)(st + o0) = rg[0];        *(uint4*)(st + 2560 + o0) = rg[1];
        *(uint4*)(st + 5120 + o0) = rg[2]; *(uint4*)(st + 7680 + o0) = rg[3];
        *(uint4*)(st + o1) = rg[4];        *(uint4*)(st + 2560 + o1) = rg[5];
        *(uint4*)(st + 5120 + o1) = rg[6]; *(uint4*)(st + 7680 + o1) = rg[7];
    }
    __syncthreads();

    for (int c = 0; c < 24; c++) {
        int s = c & 1;
        if (c < 23) {
            const uint32_t off = (c + 1) * 16 + kq_l * 4;
            size_t ar0 = (size_t)(m0 + row_l) * GK768_U32 + off;
            size_t br0 = (size_t)(n0 + row_l) * GK768_U32 + off;
            size_t ar1 = (size_t)(m0 + row_h) * GK768_U32 + off;
            size_t br1 = (size_t)(n0 + row_h) * GK768_U32 + off;
            rg[0] = *(const uint4*)(Ahi + ar0); rg[1] = *(const uint4*)(Alo + ar0);
            rg[2] = *(const uint4*)(Bhi + br0); rg[3] = *(const uint4*)(Blo + br0);
            rg[4] = *(const uint4*)(Ahi + ar1); rg[5] = *(const uint4*)(Alo + ar1);
            rg[6] = *(const uint4*)(Bhi + br1); rg[7] = *(const uint4*)(Blo + br1);
        }
        const uint32_t* st = sm + s * STAGE_U32;
        const uint32_t* Ah = st;
        const uint32_t* Al = st + 2560;
        const uint32_t* Bh = st + 5120;
        const uint32_t* Bl = st + 7680;
        #pragma unroll
        for (int ks = 0; ks < 2; ks++) {
            int kp = ks * 8 + tg;
            uint32_t ah[4][4], al[4][4], bh[4][2], bl[4][2];
            #pragma unroll
            for (int mi = 0; mi < 4; mi++) {
                int r0 = wm * 64 + mi * 16 + g;
                ah[mi][0] = Ah[r0 * SROW + kp];
                ah[mi][1] = Ah[(r0 + 8) * SROW + kp];
                ah[mi][2] = Ah[r0 * SROW + kp + 4];
                ah[mi][3] = Ah[(r0 + 8) * SROW + kp + 4];
                al[mi][0] = Al[r0 * SROW + kp];
                al[mi][1] = Al[(r0 + 8) * SROW + kp];
                al[mi][2] = Al[r0 * SROW + kp + 4];
                al[mi][3] = Al[(r0 + 8) * SROW + kp + 4];
            }
            #pragma unroll
            for (int ni = 0; ni < 4; ni++) {
                int rb = wn * 32 + ni * 8 + g;
                bh[ni][0] = Bh[rb * SROW + kp];
                bh[ni][1] = Bh[rb * SROW + kp + 4];
                bl[ni][0] = Bl[rb * SROW + kp];
                bl[ni][1] = Bl[rb * SROW + kp + 4];
            }
            #pragma unroll
            for (int mi = 0; mi < 4; mi++)
                #pragma unroll
                for (int ni = 0; ni < 4; ni++) {
                    mma_bf16(C[mi][ni], ah[mi], bh[ni]);
                    mma_bf16(C[mi][ni], al[mi], bh[ni]);
                    mma_bf16(C[mi][ni], ah[mi], bl[ni]);
                }
        }
        if (c < 23) {
            uint32_t* stn = sm + (s ^ 1) * STAGE_U32;
            uint32_t o0 = row_l * SROW + kq_l * 4;
            uint32_t o1 = row_h * SROW + kq_h * 4;
            *(uint4*)(stn + o0) = rg[0];        *(uint4*)(stn + 2560 + o0) = rg[1];
            *(uint4*)(stn + 5120 + o0) = rg[2]; *(uint4*)(stn + 7680 + o0) = rg[3];
            *(uint4*)(stn + o1) = rg[4];        *(uint4*)(stn + 2560 + o1) = rg[5];
            *(uint4*)(stn + 5120 + o1) = rg[6]; *(uint4*)(stn + 7680 + o1) = rg[7];
            __syncthreads();
        }
    }

    // ------------------------------ epilogue ------------------------------
    int sct = 0, dbase = 0;
    const float* wb;
    float* dst;
    if (MODE == 0) {
        sct = n0 / Cdim;                    // 0,1,2 (tiles never straddle)
        dbase = n0 - sct * Cdim;
        wb  = (sct == 0) ? wb_q : (sct == 1) ? wb_k : wb_v;
        dst = (sct == 0) ? oq : (sct == 1) ? ok : ov;
    } else {
        wb = wb_q; dst = oq;
    }
    #pragma unroll
    for (int mi = 0; mi < 4; mi++) {
        int m_a = m0 + wm * 64 + mi * 16 + g;
        int m_b = m_a + 8;
        float xl0[8], xl1[8];
        {
            const float* xr0 = xa + (size_t)m_a * xa_stride + ((MODE == 0) ? sct * 8 : 0);
            const float* xr1 = xa + (size_t)m_b * xa_stride + ((MODE == 0) ? sct * 8 : 0);
            #pragma unroll
            for (int r = 0; r < 8; r++) { xl0[r] = xr0[r]; xl1[r] = xr1[r]; }
        }
        int ba = m_a >> 10, na = m_a & 1023;
        int bb = m_b >> 10, nb = m_b & 1023;
        #pragma unroll
        for (int ni = 0; ni < 4; ni++) {
            int dloc = wn * 32 + ni * 8 + tg * 2;     // within 128-tile
            int d0 = n0 + dloc;
            float2 va, vb2;
            va.x  = C[mi][ni][0] + bias[d0];
            va.y  = C[mi][ni][1] + bias[d0 + 1];
            vb2.x = C[mi][ni][2] + bias[d0];
            vb2.y = C[mi][ni][3] + bias[d0 + 1];
            int dd0 = (MODE == 0) ? (dbase + dloc) : d0;
            #pragma unroll
            for (int r = 0; r < 8; r++) {
                float w0 = wb[dd0 * 8 + r], w1 = wb[(dd0 + 1) * 8 + r];
                va.x  += xl0[r] * w0;  va.y  += xl0[r] * w1;
                vb2.x += xl1[r] * w0;  vb2.y += xl1[r] * w1;
            }
            if (MODE == 0) {
                if (sct == 0) { va.x *= SCALE; va.y *= SCALE; vb2.x *= SCALE; vb2.y *= SCALE; }
                int h = dd0 >> 6, hd = dd0 & 63;
                *(float2*)(dst + (((size_t)(ba * Hh + h) * Nseq) + na) * HD + hd) = va;
                *(float2*)(dst + (((size_t)(bb * Hh + h) * Nseq) + nb) * HD + hd) = vb2;
            } else {
                *(float2*)(dst + (size_t)m_a * Cdim + d0) = va;
                *(float2*)(dst + (size_t)m_b * Cdim + d0) = vb2;
            }
        }
    }
}

// ===========================================================================
// Attention (SIMT, unchanged): one thread per query row, q pre-scaled.
// ===========================================================================
__global__ void __launch_bounds__(128) attn_kernel(
    const float* __restrict__ Q, const float* __restrict__ Kf,
    const float* __restrict__ V, float* __restrict__ O)
{
    __shared__ float kb[64 * 64];
    __shared__ float vb[64 * 64];
    int bh = blockIdx.x >> 3;
    int qt = blockIdx.x & 7;
    int tid = threadIdx.x;

    const float* qp = Q + ((size_t)bh * Nseq + qt * 128 + tid) * HD;
    const float* kp = Kf + (size_t)bh * Nseq * HD;
    const float* vp = V  + (size_t)bh * Nseq * HD;

    float q[64], o[64];
    #pragma unroll
    for (int i = 0; i < 16; i++) {
        float4 t4 = ((const float4*)qp)[i];
        q[4*i] = t4.x; q[4*i+1] = t4.y; q[4*i+2] = t4.z; q[4*i+3] = t4.w;
    }
    #pragma unroll
    for (int d = 0; d < 64; d++) o[d] = 0.f;

    float mval = -1e30f, l = 0.f;

    for (int kt = 0; kt < 16; kt++) {
        __syncthreads();
        const float4* ksrc = (const float4*)(kp + (size_t)kt * 64 * 64);
        const float4* vsrc = (const float4*)(vp + (size_t)kt * 64 * 64);
        #pragma unroll
        for (int i = 0; i < 8; i++) {
            int idx = tid + i * 128;
            ((float4*)kb)[idx] = ksrc[idx];
            ((float4*)vb)[idx] = vsrc[idx];
        }
        __syncthreads();
        for (int j = 0; j < 64; j++) {
            const float* krow = kb + j * 64;
            float s0 = 0.f, s1 = 0.f, s2 = 0.f, s3 = 0.f;
            #pragma unroll
            for (int d = 0; d < 64; d += 4) {
                s0 += q[d]   * krow[d];
                s1 += q[d+1] * krow[d+1];
                s2 += q[d+2] * krow[d+2];
                s3 += q[d+3] * krow[d+3];
            }
            float s = (s0 + s1) + (s2 + s3);
            if (s > mval) {
                float cf = __expf(mval - s);
                mval = s;
                l *= cf;
                #pragma unroll
                for (int d = 0; d < 64; d++) o[d] *= cf;
            }
            float p = __expf(s - mval);
            l += p;
            const float* vrow = vb + j * 64;
            #pragma unroll
            for (int d = 0; d < 64; d++) o[d] += p * vrow[d];
        }
    }

    float inv = 1.f / l;
    int b = bh / Hh, h = bh % Hh;
    int nn = qt * 128 + tid;
    float* op = O + ((size_t)b * Nseq + nn) * Cdim + h * HD;
    #pragma unroll
    for (int i = 0; i < 16; i++) {
        float4 t4;
        t4.x = o[4*i]   * inv; t4.y = o[4*i+1] * inv;
        t4.z = o[4*i+2] * inv; t4.w = o[4*i+3] * inv;
        ((float4*)op)[i] = t4;
    }
}

// ===========================================================================
extern "C" void kernel_launch(void* const* d_in, const int* in_sizes, int n_in,
                              void* d_out, int out_size)
{
    const float* x      = (const float*)d_in[0];
    const float* w_qkv  = (const float*)d_in[1];
    const float* b_qkv  = (const float*)d_in[2];
    const float* w_proj = (const float*)d_in[3];
    const float* b_proj = (const float*)d_in[4];
    const float* q_a = (const float*)d_in[5];
    const float* q_b = (const float*)d_in[6];
    const float* k_a = (const float*)d_in[7];
    const float* k_b = (const float*)d_in[8];
    const float* v_a = (const float*)d_in[9];
    const float* v_b = (const float*)d_in[10];
    const float* o_a = (const float*)d_in[11];
    const float* o_b = (const float*)d_in[12];
    float* out = (float*)d_out;

    void* sym = nullptr;
    cudaGetSymbolAddress(&sym, g_scratch);
    float* base = (float*)sym;
    float* Qb = base;
    float* Kb = base + (size_t)QKV_ELEMS;
    float* Vb = base + (size_t)QKV_ELEMS * 2;
    float* Ob = base + (size_t)QKV_ELEMS * 3;
    float* XA = base + OFF_XA;
    float* OA = base + OFF_OA;
    __nv_bfloat16* xhi = (__nv_bfloat16*)(base + OFF_XHI);
    __nv_bfloat16* xlo = (__nv_bfloat16*)(base + OFF_XLO);
    __nv_bfloat16* wqh = (__nv_bfloat16*)(base + OFF_WQH);
    __nv_bfloat16* wql = (__nv_bfloat16*)(base + OFF_WQL);
    __nv_bfloat16* wph = (__nv_bfloat16*)(base + OFF_WPH);
    __nv_bfloat16* wpl = (__nv_bfloat16*)(base + OFF_WPL);
    __nv_bfloat16* ohi = (__nv_bfloat16*)(base + OFF_OHI);
    __nv_bfloat16* olo = (__nv_bfloat16*)(base + OFF_OLO);

    cudaFuncSetAttribute(gemm_bf16x3_kernel<0>, cudaFuncAttributeMaxDynamicSharedMemorySize, GEMM_SMEM);
    cudaFuncSetAttribute(gemm_bf16x3_kernel<1>, cudaFuncAttributeMaxDynamicSharedMemorySize, GEMM_SMEM);

    // split inputs to (hi, lo) bf16
    split_kernel<<<QKV_ELEMS / 1024, 256>>>(x, xhi, xlo);
    split_kernel<<<(3 * Cdim * Cdim) / 1024, 256>>>(w_qkv, wqh, wql);
    split_kernel<<<(Cdim * Cdim) / 1024, 256>>>(w_proj, wph, wpl);

    // LoRA down for q/k/v adapters: XA[m, 24]
    lora_down_kernel<<<Mrows, 768>>>(x, XA, q_a, k_a, v_a, 3);

    // QKV GEMM (bf16x3 mma) + bias + LoRA-up + scatter (+SCALE in q)
    gemm_bf16x3_kernel<0><<<dim3(18, 64), 256, GEMM_SMEM>>>(
        (const uint32_t*)xhi, (const uint32_t*)xlo,
        (const uint32_t*)wqh, (const uint32_t*)wql,
        b_qkv, XA, 24, q_b, k_b, v_b, Qb, Kb, Vb);

    // Attention
    attn_kernel<<<Bsz * Hh * 8, 128>>>(Qb, Kb, Vb, Ob);

    // LoRA down for o adapter + split O
    lora_down_kernel<<<Mrows, 768>>>(Ob, OA, o_a, o_a, o_a, 1);
    split_kernel<<<QKV_ELEMS / 1024, 256>>>(Ob, ohi, olo);

    // Output projection (bf16x3 mma) + bias + LoRA-up
    gemm_bf16x3_kernel<1><<<dim3(6, 64), 256, GEMM_SMEM>>>(
        (const uint32_t*)ohi, (const uint32_t*)olo,
        (const uint32_t*)wph, (const uint32_t*)wpl,
        b_proj, OA, 8, o_b, o_b, o_b, out, out, out);
}

// round 4
// speedup vs baseline: 2.8224x; 1.7923x over previous
#include <cuda_runtime.h>
#include <cuda_bf16.h>
#include <cstdint>

#define Bsz 8
#define Nseq 1024
#define Cdim 768
#define Hh 12
#define HD 64
#define RANK 8
#define SCALE 0.125f
#define Mrows (Bsz * Nseq)          // 8192

#define QKV_ELEMS (Bsz * Hh * Nseq * HD)   // 6291456
#define XA_ELEMS  (Mrows * 24)
#define OA_ELEMS  (Mrows * 8)

// float-slot offsets into g_scratch
#define F_O    ((size_t)0)
#define F_XA   (F_O + QKV_ELEMS)
#define F_OA   (F_XA + XA_ELEMS)
#define F_XHI  (F_OA + OA_ELEMS)
#define F_XLO  (F_XHI + QKV_ELEMS / 2)
#define F_WQH  (F_XLO + QKV_ELEMS / 2)
#define F_WQL  (F_WQH + (size_t)(3 * Cdim * Cdim) / 2)
#define F_WPH  (F_WQL + (size_t)(3 * Cdim * Cdim) / 2)
#define F_WPL  (F_WPH + (size_t)(Cdim * Cdim) / 2)
#define F_QH   (F_WPL + (size_t)(Cdim * Cdim) / 2)
#define F_QL   (F_QH + QKV_ELEMS / 2)
#define F_KH   (F_QL + QKV_ELEMS / 2)
#define F_KL   (F_KH + QKV_ELEMS / 2)
#define F_VTH  (F_KL + QKV_ELEMS / 2)
#define F_VTL  (F_VTH + QKV_ELEMS / 2)
#define F_OHI  (F_VTL + QKV_ELEMS / 2)
#define F_OLO  (F_OHI + QKV_ELEMS / 2)
#define SCRATCH_FLOATS (F_OLO + QKV_ELEMS / 2)

__device__ float g_scratch[SCRATCH_FLOATS];

// ===========================================================================
// helpers
// ===========================================================================
__device__ __forceinline__ void mma_bf16(float* c, const uint32_t* a, const uint32_t* b) {
    asm volatile("mma.sync.aligned.m16n8k16.row.col.f32.bf16.bf16.f32 "
        "{%0,%1,%2,%3}, {%4,%5,%6,%7}, {%8,%9}, {%0,%1,%2,%3};"
        : "+f"(c[0]), "+f"(c[1]), "+f"(c[2]), "+f"(c[3])
        : "r"(a[0]), "r"(a[1]), "r"(a[2]), "r"(a[3]), "r"(b[0]), "r"(b[1]));
}

__device__ __forceinline__ void splitpair(float x, float y, uint32_t& hi, uint32_t& lo) {
    __nv_bfloat162 h, l;
    h.x = __float2bfloat16(x);
    h.y = __float2bfloat16(y);
    l.x = __float2bfloat16(x - __bfloat162float(h.x));
    l.y = __float2bfloat16(y - __bfloat162float(h.y));
    hi = *reinterpret_cast<uint32_t*>(&h);
    lo = *reinterpret_cast<uint32_t*>(&l);
}

// ===========================================================================
// bf16 split: hi = bf16(v), lo = bf16(v - hi)   (for x and weights)
// ===========================================================================
__global__ void __launch_bounds__(256) split_kernel(
    const float* __restrict__ in, __nv_bfloat16* __restrict__ hi,
    __nv_bfloat16* __restrict__ lo)
{
    int i = blockIdx.x * 256 + threadIdx.x;
    float4 v = ((const float4*)in)[i];
    uint32_t h0, l0, h1, l1;
    splitpair(v.x, v.y, h0, l0);
    splitpair(v.z, v.w, h1, l1);
    ((uint32_t*)hi)[i * 2]     = h0;
    ((uint32_t*)hi)[i * 2 + 1] = h1;
    ((uint32_t*)lo)[i * 2]     = l0;
    ((uint32_t*)lo)[i * 2 + 1] = l1;
}

// ===========================================================================
// LoRA down-projection
// ===========================================================================
__global__ void __launch_bounds__(768) lora_down_kernel(
    const float* __restrict__ in, float* __restrict__ out,
    const float* __restrict__ a0, const float* __restrict__ a1,
    const float* __restrict__ a2, int nA)
{
    __shared__ float row[Cdim];
    int n = blockIdx.x;
    row[threadIdx.x] = in[(size_t)n * Cdim + threadIdx.x];
    __syncthreads();
    int w = threadIdx.x >> 5, lane = threadIdx.x & 31;
    int nDots = nA * 8;
    if (w < nDots) {
        const float* a = ((w < 8) ? a0 : (w < 16) ? a1 : a2) + (size_t)(w & 7) * Cdim;
        float s = 0.f;
        #pragma unroll
        for (int c = lane; c < Cdim; c += 32) s += row[c] * a[c];
        #pragma unroll
        for (int off = 16; off; off >>= 1) s += __shfl_xor_sync(0xffffffffu, s, off);
        if (lane == 0) out[(size_t)n * nDots + w] = s;
    }
}

// ===========================================================================
// bf16x3 NT GEMM via mma.sync, 128x128 tile, BK=32, 8 warps.
// MODE 0: qkv epilogue -> writes Q/K hi,lo bf16 [bh][n][hd] and V hi,lo
//         transposed [bh][hd][n]; q scaled by SCALE. No fp32 output.
// MODE 1: proj epilogue -> fp32 out row-major.
// ===========================================================================
#define GK768_U32 384
#define SROW 20
#define STAGE_U32 (4 * 128 * SROW)
#define GEMM_SMEM (2 * STAGE_U32 * 4)

template <int MODE>
__global__ void __launch_bounds__(256) gemm_bf16x3_kernel(
    const uint32_t* __restrict__ Ahi, const uint32_t* __restrict__ Alo,
    const uint32_t* __restrict__ Bhi, const uint32_t* __restrict__ Blo,
    const float* __restrict__ bias,
    const float* __restrict__ xa, int xa_stride,
    const float* __restrict__ wb_q, const float* __restrict__ wb_k,
    const float* __restrict__ wb_v,
    float* __restrict__ outf,
    uint32_t* __restrict__ Qho, uint32_t* __restrict__ Qlo2,
    uint32_t* __restrict__ Kho, uint32_t* __restrict__ Klo2,
    __nv_bfloat16* __restrict__ Vtho, __nv_bfloat16* __restrict__ Vtlo)
{
    extern __shared__ uint32_t sm[];
    int tid = threadIdx.x;
    int wid = tid >> 5, lane = tid & 31;
    int wm = wid >> 2, wn = wid & 3;
    int m0 = blockIdx.y * 128, n0 = blockIdx.x * 128;
    int g = lane >> 2, tg = lane & 3;

    float C[4][4][4];
    #pragma unroll
    for (int a = 0; a < 4; a++)
        #pragma unroll
        for (int b = 0; b < 4; b++)
            #pragma unroll
            for (int q = 0; q < 4; q++) C[a][b][q] = 0.f;

    int row_l = tid >> 2, kq_l = tid & 3;
    int row_h = (tid + 256) >> 2, kq_h = tid & 3;

    uint4 rg[8];
    {
        const uint32_t off = kq_l * 4;
        size_t ar0 = (size_t)(m0 + row_l) * GK768_U32 + off;
        size_t br0 = (size_t)(n0 + row_l) * GK768_U32 + off;
        size_t ar1 = (size_t)(m0 + row_h) * GK768_U32 + off;
        size_t br1 = (size_t)(n0 + row_h) * GK768_U32 + off;
        rg[0] = *(const uint4*)(Ahi + ar0); rg[1] = *(const uint4*)(Alo + ar0);
        rg[2] = *(const uint4*)(Bhi + br0); rg[3] = *(const uint4*)(Blo + br0);
        rg[4] = *(const uint4*)(Ahi + ar1); rg[5] = *(const uint4*)(Alo + ar1);
        rg[6] = *(const uint4*)(Bhi + br1); rg[7] = *(const uint4*)(Blo + br1);
    }
    {
        uint32_t* st = sm;
        uint32_t o0 = row_l * SROW + kq_l * 4;
        uint32_t o1 = row_h * SROW + kq_h * 4;
        *(uint4*)(st + o0) = rg[0];        *(uint4*)(st + 2560 + o0) = rg[1];
        *(uint4*)(st + 5120 + o0) = rg[2]; *(uint4*)(st + 7680 + o0) = rg[3];
        *(uint4*)(st + o1) = rg[4];        *(uint4*)(st + 2560 + o1) = rg[5];
        *(uint4*)(st + 5120 + o1) = rg[6]; *(uint4*)(st + 7680 + o1) = rg[7];
    }
    __syncthreads();

    for (int c = 0; c < 24; c++) {
        int s = c & 1;
        if (c < 23) {
            const uint32_t off = (c + 1) * 16 + kq_l * 4;
            size_t ar0 = (size_t)(m0 + row_l) * GK768_U32 + off;
            size_t br0 = (size_t)(n0 + row_l) * GK768_U32 + off;
            size_t ar1 = (size_t)(m0 + row_h) * GK768_U32 + off;
            size_t br1 = (size_t)(n0 + row_h) * GK768_U32 + off;
            rg[0] = *(const uint4*)(Ahi + ar0); rg[1] = *(const uint4*)(Alo + ar0);
            rg[2] = *(const uint4*)(Bhi + br0); rg[3] = *(const uint4*)(Blo + br0);
            rg[4] = *(const uint4*)(Ahi + ar1); rg[5] = *(const uint4*)(Alo + ar1);
            rg[6] = *(const uint4*)(Bhi + br1); rg[7] = *(const uint4*)(Blo + br1);
        }
        const uint32_t* st = sm + s * STAGE_U32;
        const uint32_t* Ah = st;
        const uint32_t* Al = st + 2560;
        const uint32_t* Bh = st + 5120;
        const uint32_t* Bl = st + 7680;
        #pragma unroll
        for (int ks = 0; ks < 2; ks++) {
            int kp = ks * 8 + tg;
            uint32_t ah[4][4], al[4][4], bh[4][2], bl[4][2];
            #pragma unroll
            for (int mi = 0; mi < 4; mi++) {
                int r0 = wm * 64 + mi * 16 + g;
                ah[mi][0] = Ah[r0 * SROW + kp];
                ah[mi][1] = Ah[(r0 + 8) * SROW + kp];
                ah[mi][2] = Ah[r0 * SROW + kp + 4];
                ah[mi][3] = Ah[(r0 + 8) * SROW + kp + 4];
                al[mi][0] = Al[r0 * SROW + kp];
                al[mi][1] = Al[(r0 + 8) * SROW + kp];
                al[mi][2] = Al[r0 * SROW + kp + 4];
                al[mi][3] = Al[(r0 + 8) * SROW + kp + 4];
            }
            #pragma unroll
            for (int ni = 0; ni < 4; ni++) {
                int rb = wn * 32 + ni * 8 + g;
                bh[ni][0] = Bh[rb * SROW + kp];
                bh[ni][1] = Bh[rb * SROW + kp + 4];
                bl[ni][0] = Bl[rb * SROW + kp];
                bl[ni][1] = Bl[rb * SROW + kp + 4];
            }
            #pragma unroll
            for (int mi = 0; mi < 4; mi++)
                #pragma unroll
                for (int ni = 0; ni < 4; ni++) {
                    mma_bf16(C[mi][ni], ah[mi], bh[ni]);
                    mma_bf16(C[mi][ni], al[mi], bh[ni]);
                    mma_bf16(C[mi][ni], ah[mi], bl[ni]);
                }
        }
        if (c < 23) {
            uint32_t* stn = sm + (s ^ 1) * STAGE_U32;
            uint32_t o0 = row_l * SROW + kq_l * 4;
            uint32_t o1 = row_h * SROW + kq_h * 4;
            *(uint4*)(stn + o0) = rg[0];        *(uint4*)(stn + 2560 + o0) = rg[1];
            *(uint4*)(stn + 5120 + o0) = rg[2]; *(uint4*)(stn + 7680 + o0) = rg[3];
            *(uint4*)(stn + o1) = rg[4];        *(uint4*)(stn + 2560 + o1) = rg[5];
            *(uint4*)(stn + 5120 + o1) = rg[6]; *(uint4*)(stn + 7680 + o1) = rg[7];
            __syncthreads();
        }
    }

    // ------------------------------ epilogue ------------------------------
    int sct = 0, dbase = 0;
    const float* wb;
    if (MODE == 0) {
        sct = n0 / Cdim;
        dbase = n0 - sct * Cdim;
        wb = (sct == 0) ? wb_q : (sct == 1) ? wb_k : wb_v;
    } else {
        wb = wb_q;
    }
    #pragma unroll
    for (int mi = 0; mi < 4; mi++) {
        int m_a = m0 + wm * 64 + mi * 16 + g;
        int m_b = m_a + 8;
        float xl0[8], xl1[8];
        {
            const float* xr0 = xa + (size_t)m_a * xa_stride + ((MODE == 0) ? sct * 8 : 0);
            const float* xr1 = xa + (size_t)m_b * xa_stride + ((MODE == 0) ? sct * 8 : 0);
            #pragma unroll
            for (int r = 0; r < 8; r++) { xl0[r] = xr0[r]; xl1[r] = xr1[r]; }
        }
        int ba = m_a >> 10, na = m_a & 1023;
        int bb = m_b >> 10, nb = m_b & 1023;
        #pragma unroll
        for (int ni = 0; ni < 4; ni++) {
            int dloc = wn * 32 + ni * 8 + tg * 2;
            int d0 = n0 + dloc;
            float2 va, vb2;
            va.x  = C[mi][ni][0] + bias[d0];
            va.y  = C[mi][ni][1] + bias[d0 + 1];
            vb2.x = C[mi][ni][2] + bias[d0];
            vb2.y = C[mi][ni][3] + bias[d0 + 1];
            int dd0 = (MODE == 0) ? (dbase + dloc) : d0;
            #pragma unroll
            for (int r = 0; r < 8; r++) {
                float w0 = wb[dd0 * 8 + r], w1 = wb[(dd0 + 1) * 8 + r];
                va.x  += xl0[r] * w0;  va.y  += xl0[r] * w1;
                vb2.x += xl1[r] * w0;  vb2.y += xl1[r] * w1;
            }
            if (MODE == 0) {
                int h = dd0 >> 6, hd = dd0 & 63;
                if (sct == 0) { va.x *= SCALE; va.y *= SCALE; vb2.x *= SCALE; vb2.y *= SCALE; }
                if (sct < 2) {
                    uint32_t *th = (sct == 0) ? Qho : Kho;
                    uint32_t *tl = (sct == 0) ? Qlo2 : Klo2;
                    uint32_t hA, lA, hB, lB;
                    splitpair(va.x, va.y, hA, lA);
                    splitpair(vb2.x, vb2.y, hB, lB);
                    size_t iA = (((size_t)(ba * Hh + h) * Nseq) + na) * 32 + (hd >> 1);
                    size_t iB = (((size_t)(bb * Hh + h) * Nseq) + nb) * 32 + (hd >> 1);
                    th[iA] = hA; tl[iA] = lA;
                    th[iB] = hB; tl[iB] = lB;
                } else {
                    // V transposed [bh][hd][n], scalar bf16 stores
                    size_t base_a = ((size_t)(ba * Hh + h) * HD + hd) * Nseq + na;
                    size_t base_b = ((size_t)(bb * Hh + h) * HD + hd) * Nseq + nb;
                    __nv_bfloat16 h0 = __float2bfloat16(va.x);
                    Vtho[base_a] = h0;
                    Vtlo[base_a] = __float2bfloat16(va.x - __bfloat162float(h0));
                    __nv_bfloat16 h1 = __float2bfloat16(va.y);
                    Vtho[base_a + Nseq] = h1;
                    Vtlo[base_a + Nseq] = __float2bfloat16(va.y - __bfloat162float(h1));
                    __nv_bfloat16 h2 = __float2bfloat16(vb2.x);
                    Vtho[base_b] = h2;
                    Vtlo[base_b] = __float2bfloat16(vb2.x - __bfloat162float(h2));
                    __nv_bfloat16 h3 = __float2bfloat16(vb2.y);
                    Vtho[base_b + Nseq] = h3;
                    Vtlo[base_b + Nseq] = __float2bfloat16(vb2.y - __bfloat162float(h3));
                }
            } else {
                *(float2*)(outf + (size_t)m_a * Cdim + d0) = va;
                *(float2*)(outf + (size_t)m_b * Cdim + d0) = vb2;
            }
        }
    }
}

// ===========================================================================
// Flash attention via mma.sync bf16x3.
// CTA: 128 queries (8 warps x 16 rows), loops 8 tiles of 128 keys.
// Writes fp32 O [b][n][C] (heads interleaved) + Ohi/Olo bf16 for proj GEMM.
// ===========================================================================
#define KS_STRIDE 36               // u32 stride for K smem rows (32 + pad4)
#define VS_STRIDE 68               // u32 stride for Vt smem rows (64 + pad4)
#define ATT_SMEM_U32 (2 * 128 * KS_STRIDE + 2 * 64 * VS_STRIDE)  // 17920
#define ATT_SMEM (ATT_SMEM_U32 * 4)                              // 71680

__global__ void __launch_bounds__(256) attn_mma_kernel(
    const uint32_t* __restrict__ Qh, const uint32_t* __restrict__ Ql,
    const uint32_t* __restrict__ Kh, const uint32_t* __restrict__ Kl,
    const uint32_t* __restrict__ Vth, const uint32_t* __restrict__ Vtl,
    float* __restrict__ O, uint32_t* __restrict__ Ohi, uint32_t* __restrict__ Olo)
{
    extern __shared__ uint32_t sm[];
    uint32_t* Khs = sm;                         // 128 x 36
    uint32_t* Kls = sm + 128 * KS_STRIDE;
    uint32_t* Vhs = sm + 2 * 128 * KS_STRIDE;   // 64 x 68
    uint32_t* Vls = Vhs + 64 * VS_STRIDE;

    int bh = blockIdx.y, qt = blockIdx.x;
    int tid = threadIdx.x, wid = tid >> 5, lane = tid & 31;
    int g = lane >> 2, tg = lane & 3;

    // Q fragments (hi/lo), rows wid*16 + {g, g+8}
    uint32_t qh[4][4], ql[4][4];
    {
        const uint32_t* qb  = Qh + ((size_t)bh * Nseq + qt * 128 + wid * 16) * 32;
        const uint32_t* qb2 = Ql + ((size_t)bh * Nseq + qt * 128 + wid * 16) * 32;
        #pragma unroll
        for (int ks = 0; ks < 4; ks++) {
            int c0 = ks * 8 + tg;
            qh[ks][0] = qb[g * 32 + c0];        qh[ks][1] = qb[(g + 8) * 32 + c0];
            qh[ks][2] = qb[g * 32 + c0 + 4];    qh[ks][3] = qb[(g + 8) * 32 + c0 + 4];
            ql[ks][0] = qb2[g * 32 + c0];       ql[ks][1] = qb2[(g + 8) * 32 + c0];
            ql[ks][2] = qb2[g * 32 + c0 + 4];   ql[ks][3] = qb2[(g + 8) * 32 + c0 + 4];
        }
    }

    float Oa[8][4];
    #pragma unroll
    for (int i = 0; i < 8; i++)
        #pragma unroll
        for (int j = 0; j < 4; j++) Oa[i][j] = 0.f;
    float mr0 = -1e30f, mr1 = -1e30f, lr0 = 0.f, lr1 = 0.f;

    const uint32_t* kgh = Kh  + (size_t)bh * Nseq * 32;
    const uint32_t* kgl = Kl  + (size_t)bh * Nseq * 32;
    const uint32_t* vgh = Vth + (size_t)bh * HD * 512;
    const uint32_t* vgl = Vtl + (size_t)bh * HD * 512;

    for (int kt = 0; kt < 8; kt++) {
        __syncthreads();
        #pragma unroll
        for (int i = 0; i < 4; i++) {
            int f = tid + i * 256;             // 0..1023 (uint4 units)
            int key = f >> 3, c = f & 7;
            *(uint4*)(Khs + key * KS_STRIDE + c * 4) =
                *(const uint4*)(kgh + ((size_t)(kt * 128 + key)) * 32 + c * 4);
            *(uint4*)(Kls + key * KS_STRIDE + c * 4) =
                *(const uint4*)(kgl + ((size_t)(kt * 128 + key)) * 32 + c * 4);
            int hd = f >> 4, c2 = f & 15;
            *(uint4*)(Vhs + hd * VS_STRIDE + c2 * 4) =
                *(const uint4*)(vgh + (size_t)hd * 512 + kt * 64 + c2 * 4);
            *(uint4*)(Vls + hd * VS_STRIDE + c2 * 4) =
                *(const uint4*)(vgl + (size_t)hd * 512 + kt * 64 + c2 * 4);
        }
        __syncthreads();

        // S = Q K^T (bf16x3), 16 nfrags of 8 keys
        float Sf[16][4];
        #pragma unroll
        for (int ni = 0; ni < 16; ni++)
            #pragma unroll
            for (int q = 0; q < 4; q++) Sf[ni][q] = 0.f;
        #pragma unroll
        for (int ni = 0; ni < 16; ni++) {
            int krow = ni * 8 + g;
            #pragma unroll
            for (int ks = 0; ks < 4; ks++) {
                uint32_t bhh[2], bll[2];
                bhh[0] = Khs[krow * KS_STRIDE + ks * 8 + tg];
                bhh[1] = Khs[krow * KS_STRIDE + ks * 8 + tg + 4];
                bll[0] = Kls[krow * KS_STRIDE + ks * 8 + tg];
                bll[1] = Kls[krow * KS_STRIDE + ks * 8 + tg + 4];
                mma_bf16(Sf[ni], qh[ks], bhh);
                mma_bf16(Sf[ni], ql[ks], bhh);
                mma_bf16(Sf[ni], qh[ks], bll);
            }
        }

        // online softmax (rows g, g+8)
        float tm0 = -1e30f, tm1 = -1e30f;
        #pragma unroll
        for (int ni = 0; ni < 16; ni++) {
            tm0 = fmaxf(tm0, fmaxf(Sf[ni][0], Sf[ni][1]));
            tm1 = fmaxf(tm1, fmaxf(Sf[ni][2], Sf[ni][3]));
        }
        tm0 = fmaxf(tm0, __shfl_xor_sync(0xffffffffu, tm0, 1));
        tm0 = fmaxf(tm0, __shfl_xor_sync(0xffffffffu, tm0, 2));
        tm1 = fmaxf(tm1, __shfl_xor_sync(0xffffffffu, tm1, 1));
        tm1 = fmaxf(tm1, __shfl_xor_sync(0xffffffffu, tm1, 2));
        float mn0 = fmaxf(mr0, tm0), mn1 = fmaxf(mr1, tm1);
        float al0 = __expf(mr0 - mn0), al1 = __expf(mr1 - mn1);
        mr0 = mn0; mr1 = mn1;
        float s0 = 0.f, s1 = 0.f;
        #pragma unroll
        for (int ni = 0; ni < 16; ni++) {
            Sf[ni][0] = __expf(Sf[ni][0] - mn0);
            Sf[ni][1] = __expf(Sf[ni][1] - mn0);
            Sf[ni][2] = __expf(Sf[ni][2] - mn1);
            Sf[ni][3] = __expf(Sf[ni][3] - mn1);
            s0 += Sf[ni][0] + Sf[ni][1];
            s1 += Sf[ni][2] + Sf[ni][3];
        }
        s0 += __shfl_xor_sync(0xffffffffu, s0, 1);
        s0 += __shfl_xor_sync(0xffffffffu, s0, 2);
        s1 += __shfl_xor_sync(0xffffffffu, s1, 1);
        s1 += __shfl_xor_sync(0xffffffffu, s1, 2);
        lr0 = lr0 * al0 + s0;
        lr1 = lr1 * al1 + s1;
        #pragma unroll
        for (int ni = 0; ni < 8; ni++) {
            Oa[ni][0] *= al0; Oa[ni][1] *= al0;
            Oa[ni][2] *= al1; Oa[ni][3] *= al1;
        }

        // O += P V  (P from Sf, bf16x3)
        #pragma unroll
        for (int j = 0; j < 8; j++) {
            uint32_t ph[4], pl[4];
            splitpair(Sf[2*j][0],   Sf[2*j][1],   ph[0], pl[0]);
            splitpair(Sf[2*j][2],   Sf[2*j][3],   ph[1], pl[1]);
            splitpair(Sf[2*j+1][0], Sf[2*j+1][1], ph[2], pl[2]);
            splitpair(Sf[2*j+1][2], Sf[2*j+1][3], ph[3], pl[3]);
            #pragma unroll
            for (int ni = 0; ni < 8; ni++) {
                int vrow = ni * 8 + g;
                uint32_t vh2[2], vl2[2];
                vh2[0] = Vhs[vrow * VS_STRIDE + j * 8 + tg];
                vh2[1] = Vhs[vrow * VS_STRIDE + j * 8 + tg + 4];
                vl2[0] = Vls[vrow * VS_STRIDE + j * 8 + tg];
                vl2[1] = Vls[vrow * VS_STRIDE + j * 8 + tg + 4];
                mma_bf16(Oa[ni], ph, vh2);
                mma_bf16(Oa[ni], pl, vh2);
                mma_bf16(Oa[ni], ph, vl2);
            }
        }
    }

    // epilogue: O fp32 [b][n][C] + bf16 hi/lo [m][C]
    float inv0 = 1.f / lr0, inv1 = 1.f / lr1;
    int b = bh / Hh, h = bh % Hh;
    int nA = qt * 128 + wid * 16 + g;
    int nB = nA + 8;
    #pragma unroll
    for (int ni = 0; ni < 8; ni++) {
        int hd = ni * 8 + tg * 2;
        float2 vA, vB;
        vA.x = Oa[ni][0] * inv0; vA.y = Oa[ni][1] * inv0;
        vB.x = Oa[ni][2] * inv1; vB.y = Oa[ni][3] * inv1;
        size_t iA = ((size_t)b * Nseq + nA) * Cdim + h * HD + hd;
        size_t iB = ((size_t)b * Nseq + nB) * Cdim + h * HD + hd;
        *(float2*)(O + iA) = vA;
        *(float2*)(O + iB) = vB;
        uint32_t hA, lA, hB, lB;
        splitpair(vA.x, vA.y, hA, lA);
        splitpair(vB.x, vB.y, hB, lB);
        Ohi[iA >> 1] = hA; Olo[iA >> 1] = lA;
        Ohi[iB >> 1] = hB; Olo[iB >> 1] = lB;
    }
}

// ===========================================================================
extern "C" void kernel_launch(void* const* d_in, const int* in_sizes, int n_in,
                              void* d_out, int out_size)
{
    const float* x      = (const float*)d_in[0];
    const float* w_qkv  = (const float*)d_in[1];
    const float* b_qkv  = (const float*)d_in[2];
    const float* w_proj = (const float*)d_in[3];
    const float* b_proj = (const float*)d_in[4];
    const float* q_a = (const float*)d_in[5];
    const float* q_b = (const float*)d_in[6];
    const float* k_a = (const float*)d_in[7];
    const float* k_b = (const float*)d_in[8];
    const float* v_a = (const float*)d_in[9];
    const float* v_b = (const float*)d_in[10];
    const float* o_a = (const float*)d_in[11];
    const float* o_b = (const float*)d_in[12];
    float* out = (float*)d_out;

    void* sym = nullptr;
    cudaGetSymbolAddress(&sym, g_scratch);
    float* base = (float*)sym;
    float* Ob = base + F_O;
    float* XA = base + F_XA;
    float* OA = base + F_OA;
    __nv_bfloat16* xhi = (__nv_bfloat16*)(base + F_XHI);
    __nv_bfloat16* xlo = (__nv_bfloat16*)(base + F_XLO);
    __nv_bfloat16* wqh = (__nv_bfloat16*)(base + F_WQH);
    __nv_bfloat16* wql = (__nv_bfloat16*)(base + F_WQL);
    __nv_bfloat16* wph = (__nv_bfloat16*)(base + F_WPH);
    __nv_bfloat16* wpl = (__nv_bfloat16*)(base + F_WPL);
    uint32_t* Qhp = (uint32_t*)(base + F_QH);
    uint32_t* Qlp = (uint32_t*)(base + F_QL);
    uint32_t* Khp = (uint32_t*)(base + F_KH);
    uint32_t* Klp = (uint32_t*)(base + F_KL);
    uint32_t* Vthp = (uint32_t*)(base + F_VTH);
    uint32_t* Vtlp = (uint32_t*)(base + F_VTL);
    uint32_t* Ohip = (uint32_t*)(base + F_OHI);
    uint32_t* Olop = (uint32_t*)(base + F_OLO);

    cudaFuncSetAttribute(gemm_bf16x3_kernel<0>, cudaFuncAttributeMaxDynamicSharedMemorySize, GEMM_SMEM);
    cudaFuncSetAttribute(gemm_bf16x3_kernel<1>, cudaFuncAttributeMaxDynamicSharedMemorySize, GEMM_SMEM);
    cudaFuncSetAttribute(attn_mma_kernel, cudaFuncAttributeMaxDynamicSharedMemorySize, ATT_SMEM);

    split_kernel<<<QKV_ELEMS / 1024, 256>>>(x, xhi, xlo);
    split_kernel<<<(3 * Cdim * Cdim) / 1024, 256>>>(w_qkv, wqh, wql);
    split_kernel<<<(Cdim * Cdim) / 1024, 256>>>(w_proj, wph, wpl);

    lora_down_kernel<<<Mrows, 768>>>(x, XA, q_a, k_a, v_a, 3);

    gemm_bf16x3_kernel<0><<<dim3(18, 64), 256, GEMM_SMEM>>>(
        (const uint32_t*)xhi, (const uint32_t*)xlo,
        (const uint32_t*)wqh, (const uint32_t*)wql,
        b_qkv, XA, 24, q_b, k_b, v_b,
        nullptr, Qhp, Qlp, Khp, Klp,
        (__nv_bfloat16*)Vthp, (__nv_bfloat16*)Vtlp);

    attn_mma_kernel<<<dim3(8, Bsz * Hh), 256, ATT_SMEM>>>(
        Qhp, Qlp, Khp, Klp, Vthp, Vtlp, Ob, Ohip, Olop);

    lora_down_kernel<<<Mrows, 768>>>(Ob, OA, o_a, o_a, o_a, 1);

    gemm_bf16x3_kernel<1><<<dim3(6, 64), 256, GEMM_SMEM>>>(
        Ohip, Olop, (const uint32_t*)wph, (const uint32_t*)wpl,
        b_proj, OA, 8, o_b, o_b, o_b,
        out, nullptr, nullptr, nullptr, nullptr, nullptr, nullptr);
}